// round 11
// baseline (speedup 1.0000x reference)
#include <cuda_runtime.h>
#include <cuda_bf16.h>
#include <cstdint>

#define EMBED  1024
#define NHEAD  16
#define HDIM   64
#define BATCH  2
#define SEQ    2048
#define M_TOK  4096
#define SCL2E  0.18033688011112042f   // 0.125 * log2(e)

// ---------------------------------------------------------------------------
// Scratch (device globals — no allocation allowed)
// ---------------------------------------------------------------------------
#define NELEM ((size_t)M_TOK * EMBED)
__device__ __nv_bfloat16 g_xhi[NELEM], g_xlo[NELEM];
__device__ __nv_bfloat16 g_qhi[NELEM], g_qlo[NELEM];      // [b,h,n,d]
__device__ __nv_bfloat16 g_khi[NELEM], g_klo[NELEM];      // [b,h,n,d]
__device__ __nv_bfloat16 g_vhi[NELEM], g_vlo[NELEM];      // [b,h,d,n]
__device__ __nv_bfloat16 g_ahi[NELEM], g_alo[NELEM];      // attn out [tok][C]
__device__ __nv_bfloat16 g_wqkvT_hi[(size_t)3*EMBED*EMBED], g_wqkvT_lo[(size_t)3*EMBED*EMBED];
__device__ __nv_bfloat16 g_wprjT_hi[(size_t)EMBED*EMBED],   g_wprjT_lo[(size_t)EMBED*EMBED];

// ---------------------------------------------------------------------------
// Asm helpers (base-target safe)
// ---------------------------------------------------------------------------
__device__ __forceinline__ uint32_t smem_u32(const void* p) {
    uint32_t a;
    asm("{ .reg .u64 t; cvta.to.shared.u64 t, %1; cvt.u32.u64 %0, t; }" : "=r"(a) : "l"(p));
    return a;
}
#define CP_ASYNC16(s, g) \
    asm volatile("cp.async.cg.shared.global [%0], [%1], 16;" :: "r"(s), "l"(g))
#define CP_COMMIT() asm volatile("cp.async.commit_group;" ::: "memory")
#define CP_WAIT(n)  asm volatile("cp.async.wait_group %0;" :: "n"(n) : "memory")

#define LDMATRIX_X4(r0, r1, r2, r3, a) \
    asm volatile("ldmatrix.sync.aligned.m8n8.x4.shared.b16 {%0,%1,%2,%3}, [%4];" \
                 : "=r"(r0), "=r"(r1), "=r"(r2), "=r"(r3) : "r"(a))

#define MMA16816(c0, c1, c2, c3, a0, a1, a2, a3, b0, b1) \
    asm volatile("mma.sync.aligned.m16n8k16.row.col.f32.bf16.bf16.f32 " \
                 "{%0,%1,%2,%3}, {%4,%5,%6,%7}, {%8,%9}, {%0,%1,%2,%3};" \
                 : "+f"(c0), "+f"(c1), "+f"(c2), "+f"(c3) \
                 : "r"(a0), "r"(a1), "r"(a2), "r"(a3), "r"(b0), "r"(b1))

// exp2 on the FMA pipe (no MUFU)
__device__ __forceinline__ float fexp2(float t) {
    t = fmaxf(t, -30.0f);
    float r = t + 12582912.0f;
    float i = r - 12582912.0f;
    float x = (t - i) * 0.6931471805599453f;
    float p = fmaf(x, 0.0083333333f, 0.0416666667f);
    p = fmaf(x, p, 0.1666666667f);
    p = fmaf(x, p, 0.5f);
    p = fmaf(x, p, 1.0f);
    p = fmaf(x, p, 1.0f);
    int ii = __float_as_int(r) - 0x4B400000;
    return __int_as_float(__float_as_int(p) + (ii << 23));
}

__device__ __forceinline__ void split2(float a, float b, uint32_t& hi, uint32_t& lo) {
    __nv_bfloat162 h2 = __floats2bfloat162_rn(a, b);
    float ra = a - __bfloat162float(__low2bfloat16(h2));
    float rb = b - __bfloat162float(__high2bfloat16(h2));
    __nv_bfloat162 l2 = __floats2bfloat162_rn(ra, rb);
    hi = reinterpret_cast<uint32_t&>(h2);
    lo = reinterpret_cast<uint32_t&>(l2);
}
__device__ __forceinline__ void split1(float v, __nv_bfloat16& h, __nv_bfloat16& l) {
    h = __float2bfloat16(v);
    l = __float2bfloat16(v - __bfloat162float(h));
}

// ---------------------------------------------------------------------------
// conversions
// ---------------------------------------------------------------------------
__global__ __launch_bounds__(256) void cvt_split(
    const float* __restrict__ x, __nv_bfloat16* __restrict__ hi,
    __nv_bfloat16* __restrict__ lo, int n4)
{
    int i = blockIdx.x * blockDim.x + threadIdx.x;
    if (i >= n4) return;
    float4 v = ((const float4*)x)[i];
    __nv_bfloat16 h[4], l[4];
    float f[4] = {v.x, v.y, v.z, v.w};
    #pragma unroll
    for (int j = 0; j < 4; j++) split1(f[j], h[j], l[j]);
    ((uint2*)hi)[i] = *(uint2*)h;
    ((uint2*)lo)[i] = *(uint2*)l;
}

__global__ __launch_bounds__(256) void cvt_transpose(
    const float* __restrict__ W, __nv_bfloat16* __restrict__ thi,
    __nv_bfloat16* __restrict__ tlo, int K, int N)
{
    __shared__ float t[32][33];
    int tx = threadIdx.x & 31, ty = threadIdx.x >> 5;
    int n0 = blockIdx.x * 32, k0 = blockIdx.y * 32;
    #pragma unroll
    for (int i = 0; i < 4; i++)
        t[ty + i * 8][tx] = W[(size_t)(k0 + ty + i * 8) * N + n0 + tx];
    __syncthreads();
    #pragma unroll
    for (int i = 0; i < 4; i++) {
        float v = t[tx][ty + i * 8];
        __nv_bfloat16 h, l; split1(v, h, l);
        size_t o = (size_t)(n0 + ty + i * 8) * K + k0 + tx;
        thi[o] = h; tlo[o] = l;
    }
}

// ---------------------------------------------------------------------------
// HMMA bf16x3 GEMM. Single-barrier 2-stage mainloop.
// CTA 128x128, BK=32, 8 warps (2M x 4N). 2 CTAs/SM.
// ---------------------------------------------------------------------------
#define G_BK     32
#define G_LDS    40
#define G_TILE_B (128 * G_LDS * 2)
#define G_STAGE  (4 * G_TILE_B)
#define G_SMEM   (2 * G_STAGE)

__device__ __forceinline__ void g_load_stage(
    uint32_t s_stage,
    const __nv_bfloat16* ga_hi, const __nv_bfloat16* ga_lo,
    const __nv_bfloat16* gb_hi, const __nv_bfloat16* gb_lo,
    int k0, int K, int tid)
{
    const __nv_bfloat16* srcs[4] = {ga_hi, ga_lo, gb_hi, gb_lo};
    #pragma unroll
    for (int t = 0; t < 4; t++) {
        #pragma unroll
        for (int i = 0; i < 2; i++) {
            int id = tid + i * 256;
            int r = id >> 2, c = (id & 3) << 3;
            CP_ASYNC16(s_stage + t * G_TILE_B + (uint32_t)(r * G_LDS + c) * 2,
                       srcs[t] + (size_t)r * K + k0 + c);
        }
    }
}

template <int MODE>
__global__ __launch_bounds__(256, 2) void tc_gemm(
    const __nv_bfloat16* __restrict__ Ahi, const __nv_bfloat16* __restrict__ Alo,
    const __nv_bfloat16* __restrict__ Bthi, const __nv_bfloat16* __restrict__ Btlo,
    const float* __restrict__ bias, float* __restrict__ C, int N, int K,
    __nv_bfloat16* qh_o, __nv_bfloat16* ql_o,
    __nv_bfloat16* kh_o, __nv_bfloat16* kl_o,
    __nv_bfloat16* vh_o, __nv_bfloat16* vl_o)
{
    extern __shared__ char smch[];
    const uint32_t s_base = smem_u32(smch);
    const int tid = threadIdx.x;
    const int wid = tid >> 5, lane = tid & 31;
    const int bm = blockIdx.y * 128, bn = blockIdx.x * 128;
    const int wm = (wid & 1) * 64;
    const int wn = (wid >> 1) * 32;

    const __nv_bfloat16* ga_hi = Ahi + (size_t)bm * K;
    const __nv_bfloat16* ga_lo = Alo + (size_t)bm * K;
    const __nv_bfloat16* gb_hi = Bthi + (size_t)bn * K;
    const __nv_bfloat16* gb_lo = Btlo + (size_t)bn * K;

    float acc[4][4][4];
    #pragma unroll
    for (int i = 0; i < 4; i++)
        #pragma unroll
        for (int j = 0; j < 4; j++)
            #pragma unroll
            for (int e = 0; e < 4; e++) acc[i][j][e] = 0.f;

    const int a_row = wm + (lane & 15);
    const uint32_t a_coff = (uint32_t)((lane >> 4) * 16);
    const int grp = lane >> 3;
    const int b_row = wn + ((grp & 2) << 2) + (lane & 7);
    const uint32_t b_coff = (uint32_t)((grp & 1) * 16);

    const int NT = K / G_BK;
    g_load_stage(s_base, ga_hi, ga_lo, gb_hi, gb_lo, 0, K, tid);
    CP_COMMIT();

    for (int it = 0; it < NT; it++) {
        CP_WAIT(0);
        __syncthreads();
        // prefetch AFTER the barrier: every warp has finished reading the
        // target buffer ((it+1)&1 == (it-1)&1) in iter it-1, proven by the
        // barrier above. Single barrier per iteration.
        if (it + 1 < NT) {
            g_load_stage(s_base + ((it + 1) & 1) * G_STAGE,
                         ga_hi, ga_lo, gb_hi, gb_lo, (it + 1) * G_BK, K, tid);
            CP_COMMIT();
        }

        const uint32_t st = s_base + (it & 1) * G_STAGE;
        #pragma unroll
        for (int ks = 0; ks < 2; ks++) {
            const uint32_t kb = (uint32_t)(ks * 32);
            uint32_t ah[4][4], al[4][4];
            #pragma unroll
            for (int mt = 0; mt < 4; mt++) {
                uint32_t ra = st + (uint32_t)((a_row + mt * 16) * G_LDS) * 2 + kb + a_coff;
                LDMATRIX_X4(ah[mt][0], ah[mt][1], ah[mt][2], ah[mt][3], ra);
                LDMATRIX_X4(al[mt][0], al[mt][1], al[mt][2], al[mt][3], ra + G_TILE_B);
            }
            uint32_t bh[2][4], bl[2][4];
            #pragma unroll
            for (int nt2 = 0; nt2 < 2; nt2++) {
                uint32_t rb = st + 2 * G_TILE_B +
                    (uint32_t)((b_row + nt2 * 16) * G_LDS) * 2 + kb + b_coff;
                LDMATRIX_X4(bh[nt2][0], bh[nt2][1], bh[nt2][2], bh[nt2][3], rb);
                LDMATRIX_X4(bl[nt2][0], bl[nt2][1], bl[nt2][2], bl[nt2][3], rb + G_TILE_B);
            }
            #pragma unroll
            for (int mt = 0; mt < 4; mt++) {
                #pragma unroll
                for (int nt = 0; nt < 4; nt++) {
                    float* c = acc[mt][nt];
                    MMA16816(c[0], c[1], c[2], c[3],
                             ah[mt][0], ah[mt][1], ah[mt][2], ah[mt][3],
                             bh[nt >> 1][(nt & 1) * 2], bh[nt >> 1][(nt & 1) * 2 + 1]);
                }
            }
            #pragma unroll
            for (int mt = 0; mt < 4; mt++) {
                #pragma unroll
                for (int nt = 0; nt < 4; nt++) {
                    float* c = acc[mt][nt];
                    MMA16816(c[0], c[1], c[2], c[3],
                             ah[mt][0], ah[mt][1], ah[mt][2], ah[mt][3],
                             bl[nt >> 1][(nt & 1) * 2], bl[nt >> 1][(nt & 1) * 2 + 1]);
                }
            }
            #pragma unroll
            for (int mt = 0; mt < 4; mt++) {
                #pragma unroll
                for (int nt = 0; nt < 4; nt++) {
                    float* c = acc[mt][nt];
                    MMA16816(c[0], c[1], c[2], c[3],
                             al[mt][0], al[mt][1], al[mt][2], al[mt][3],
                             bh[nt >> 1][(nt & 1) * 2], bh[nt >> 1][(nt & 1) * 2 + 1]);
                }
            }
        }
    }

    const int er = lane >> 2;
    const int ec = (lane & 3) * 2;
    #pragma unroll
    for (int nt = 0; nt < 4; nt++) {
        int col = bn + wn + nt * 8 + ec;
        float bs0 = __ldg(bias + col), bs1 = __ldg(bias + col + 1);
        if (MODE == 0) {
            #pragma unroll
            for (int mt = 0; mt < 4; mt++) {
                int row = bm + wm + mt * 16 + er;
                float2 v0 = {acc[mt][nt][0] + bs0, acc[mt][nt][1] + bs1};
                float2 v1 = {acc[mt][nt][2] + bs0, acc[mt][nt][3] + bs1};
                *(float2*)(C + (size_t)row * N + col) = v0;
                *(float2*)(C + (size_t)(row + 8) * N + col) = v1;
            }
        } else {
            int p = col >> 10;
            int hh = (col & 1023) >> 6;
            int d = col & 63;
            #pragma unroll
            for (int mt = 0; mt < 4; mt++) {
                int row = bm + wm + mt * 16 + er;
                int bb = row >> 11, n = row & 2047;
                float v0 = acc[mt][nt][0] + bs0, v1 = acc[mt][nt][1] + bs1;
                float v2 = acc[mt][nt][2] + bs0, v3 = acc[mt][nt][3] + bs1;
                if (p == 0) { v0 *= SCL2E; v1 *= SCL2E; v2 *= SCL2E; v3 *= SCL2E; }
                if (p < 2) {
                    __nv_bfloat16* dh = p ? kh_o : qh_o;
                    __nv_bfloat16* dl = p ? kl_o : ql_o;
                    size_t i0 = ((size_t)(bb * NHEAD + hh) * SEQ + n) * HDIM + d;
                    uint32_t hi, lo;
                    split2(v0, v1, hi, lo);
                    *(uint32_t*)(dh + i0) = hi;  *(uint32_t*)(dl + i0) = lo;
                    split2(v2, v3, hi, lo);
                    *(uint32_t*)(dh + i0 + 8 * HDIM) = hi;  *(uint32_t*)(dl + i0 + 8 * HDIM) = lo;
                } else {
                    size_t i0 = ((size_t)(bb * NHEAD + hh) * HDIM + d) * SEQ + n;
                    __nv_bfloat16 h, l;
                    split1(v0, h, l); vh_o[i0] = h;            vl_o[i0] = l;
                    split1(v1, h, l); vh_o[i0 + SEQ] = h;      vl_o[i0 + SEQ] = l;
                    split1(v2, h, l); vh_o[i0 + 8] = h;        vl_o[i0 + 8] = l;
                    split1(v3, h, l); vh_o[i0 + SEQ + 8] = h;  vl_o[i0 + SEQ + 8] = l;
                }
            }
        }
    }
}

// ---------------------------------------------------------------------------
// HMMA flash attention (bf16 3-term). CTA = 128 q rows; 8 warps x 16 rows.
// Q-hi AND Q-lo fragments cached in registers (loaded once).
// ---------------------------------------------------------------------------
#define A_LDS    72
#define AQ_TILE  (128 * A_LDS * 2)          // 18432 B per Q array
#define AKV_TILE (64 * A_LDS * 2)           // 9216 B per KV array
#define A_ST0    (2 * AQ_TILE)              // 36864
#define A_STAGE  (4 * AKV_TILE)             // 36864
#define A_SMEM   (A_ST0 + 2 * A_STAGE)      // 110592 B

__global__ __launch_bounds__(256, 2) void attn_mma(
    const __nv_bfloat16* __restrict__ qhi, const __nv_bfloat16* __restrict__ qlo,
    const __nv_bfloat16* __restrict__ khi, const __nv_bfloat16* __restrict__ klo,
    const __nv_bfloat16* __restrict__ vhi, const __nv_bfloat16* __restrict__ vlo,
    __nv_bfloat16* __restrict__ ohi, __nv_bfloat16* __restrict__ olo)
{
    extern __shared__ char smch[];
    const uint32_t sb = smem_u32(smch);
    const int tid = threadIdx.x, wid = tid >> 5, lane = tid & 31;
    const int b = blockIdx.z, h = blockIdx.y, q0 = blockIdx.x * 128;
    const size_t bh = (size_t)(b * NHEAD + h);

    const __nv_bfloat16* gq_h = qhi + (bh * SEQ + q0) * HDIM;
    const __nv_bfloat16* gq_l = qlo + (bh * SEQ + q0) * HDIM;
    const __nv_bfloat16* gk_h = khi + bh * SEQ * HDIM;
    const __nv_bfloat16* gk_l = klo + bh * SEQ * HDIM;
    const __nv_bfloat16* gv_h = vhi + bh * HDIM * SEQ;
    const __nv_bfloat16* gv_l = vlo + bh * HDIM * SEQ;

    #pragma unroll
    for (int i = 0; i < 8; i++) {
        int id = tid + i * 256;
        int arr = id >> 10, rem = id & 1023;
        int r = rem >> 3, c = (rem & 7) * 8;
        uint32_t dst = sb + arr * AQ_TILE + (uint32_t)(r * A_LDS + c) * 2;
        CP_ASYNC16(dst, (arr ? gq_l : gq_h) + (size_t)r * HDIM + c);
    }
    {
        uint32_t st = sb + A_ST0;
        #pragma unroll
        for (int i = 0; i < 8; i++) {
            int id = tid + i * 256;
            int arr = id >> 9, rem = id & 511;
            int r = rem >> 3, c = (rem & 7) * 8;
            uint32_t dst = st + arr * AKV_TILE + (uint32_t)(r * A_LDS + c) * 2;
            const __nv_bfloat16* src;
            if      (arr == 0) src = gk_h + (size_t)r * HDIM + c;
            else if (arr == 1) src = gk_l + (size_t)r * HDIM + c;
            else if (arr == 2) src = gv_h + (size_t)r * SEQ + c;
            else               src = gv_l + (size_t)r * SEQ + c;
            CP_ASYNC16(dst, src);
        }
    }
    CP_COMMIT();

    const int g = lane >> 3, rr = lane & 7;
    const int a_ro = wid * 16 + ((g & 1) << 3) + rr;
    const int a_co = (g >> 1) << 3;
    const int b_ro = ((g >> 1) << 3) + rr;
    const int b_co = (g & 1) << 3;

    uint32_t qh_[4][4], ql_[4][4];
    float o[8][4];
    #pragma unroll
    for (int j = 0; j < 8; j++)
        #pragma unroll
        for (int e = 0; e < 4; e++) o[j][e] = 0.f;
    float m0 = -1e30f, m1 = -1e30f, l0 = 0.f, l1 = 0.f;

    const int NT = SEQ / 64;
    for (int t = 0; t < NT; t++) {
        CP_WAIT(0);
        __syncthreads();

        if (t + 1 < NT) {
            uint32_t st = sb + A_ST0 + ((t + 1) & 1) * A_STAGE;
            int kv0 = (t + 1) * 64;
            #pragma unroll
            for (int i = 0; i < 8; i++) {
                int id = tid + i * 256;
                int arr = id >> 9, rem = id & 511;
                int r = rem >> 3, c = (rem & 7) * 8;
                uint32_t dst = st + arr * AKV_TILE + (uint32_t)(r * A_LDS + c) * 2;
                const __nv_bfloat16* src;
                if      (arr == 0) src = gk_h + (size_t)(kv0 + r) * HDIM + c;
                else if (arr == 1) src = gk_l + (size_t)(kv0 + r) * HDIM + c;
                else if (arr == 2) src = gv_h + (size_t)r * SEQ + kv0 + c;
                else               src = gv_l + (size_t)r * SEQ + kv0 + c;
                CP_ASYNC16(dst, src);
            }
            CP_COMMIT();
        }

        if (t == 0) {
            #pragma unroll
            for (int ks = 0; ks < 4; ks++) {
                uint32_t ad = sb + (uint32_t)(a_ro * A_LDS + ks * 16 + a_co) * 2;
                LDMATRIX_X4(qh_[ks][0], qh_[ks][1], qh_[ks][2], qh_[ks][3], ad);
                LDMATRIX_X4(ql_[ks][0], ql_[ks][1], ql_[ks][2], ql_[ks][3], ad + AQ_TILE);
            }
        }

        const uint32_t stb = sb + A_ST0 + (t & 1) * A_STAGE;

        // ---- S = Q' @ K^T (3-split), interleaved sa/sc chains ----
        float s[8][4];
        #pragma unroll
        for (int j = 0; j < 8; j++)
            #pragma unroll
            for (int e = 0; e < 4; e++) s[j][e] = 0.f;

        #pragma unroll
        for (int ks = 0; ks < 4; ks++) {
            #pragma unroll
            for (int np = 0; np < 4; np++) {
                uint32_t ka = stb + (uint32_t)((np * 16 + b_ro) * A_LDS + ks * 16 + b_co) * 2;
                uint32_t k0, k1, k2, k3, e0, e1, e2, e3;
                LDMATRIX_X4(k0, k1, k2, k3, ka);
                LDMATRIX_X4(e0, e1, e2, e3, ka + AKV_TILE);
                float* sa = s[2 * np]; float* sc = s[2 * np + 1];
                MMA16816(sa[0], sa[1], sa[2], sa[3],
                         qh_[ks][0], qh_[ks][1], qh_[ks][2], qh_[ks][3], k0, k1);
                MMA16816(sc[0], sc[1], sc[2], sc[3],
                         qh_[ks][0], qh_[ks][1], qh_[ks][2], qh_[ks][3], k2, k3);
                MMA16816(sa[0], sa[1], sa[2], sa[3],
                         qh_[ks][0], qh_[ks][1], qh_[ks][2], qh_[ks][3], e0, e1);
                MMA16816(sc[0], sc[1], sc[2], sc[3],
                         qh_[ks][0], qh_[ks][1], qh_[ks][2], qh_[ks][3], e2, e3);
                MMA16816(sa[0], sa[1], sa[2], sa[3],
                         ql_[ks][0], ql_[ks][1], ql_[ks][2], ql_[ks][3], k0, k1);
                MMA16816(sc[0], sc[1], sc[2], sc[3],
                         ql_[ks][0], ql_[ks][1], ql_[ks][2], ql_[ks][3], k2, k3);
            }
        }

        // ---- online softmax ----
        float mt0 = -1e30f, mt1 = -1e30f;
        #pragma unroll
        for (int j = 0; j < 8; j++) {
            mt0 = fmaxf(mt0, fmaxf(s[j][0], s[j][1]));
            mt1 = fmaxf(mt1, fmaxf(s[j][2], s[j][3]));
        }
        mt0 = fmaxf(mt0, __shfl_xor_sync(0xffffffffu, mt0, 1));
        mt0 = fmaxf(mt0, __shfl_xor_sync(0xffffffffu, mt0, 2));
        mt1 = fmaxf(mt1, __shfl_xor_sync(0xffffffffu, mt1, 1));
        mt1 = fmaxf(mt1, __shfl_xor_sync(0xffffffffu, mt1, 2));
        float nm0 = fmaxf(m0, mt0), nm1 = fmaxf(m1, mt1);
        float c0 = fexp2(m0 - nm0), c1 = fexp2(m1 - nm1);
        m0 = nm0; m1 = nm1;
        #pragma unroll
        for (int j = 0; j < 8; j++) {
            o[j][0] *= c0; o[j][1] *= c0; o[j][2] *= c1; o[j][3] *= c1;
        }
        float rs0 = 0.f, rs1 = 0.f;

        // ---- stream P -> PV (3-split), interleaved oa/oc chains ----
        #pragma unroll
        for (int t_ = 0; t_ < 4; t_++) {
            int j0 = 2 * t_, j1 = 2 * t_ + 1;
            float p00 = fexp2(s[j0][0] - nm0), p01 = fexp2(s[j0][1] - nm0);
            float p02 = fexp2(s[j0][2] - nm1), p03 = fexp2(s[j0][3] - nm1);
            float p10 = fexp2(s[j1][0] - nm0), p11 = fexp2(s[j1][1] - nm0);
            float p12 = fexp2(s[j1][2] - nm1), p13 = fexp2(s[j1][3] - nm1);
            rs0 += p00 + p01 + p10 + p11;
            rs1 += p02 + p03 + p12 + p13;
            uint32_t pa0, pa1, pa2, pa3, pb0, pb1, pb2, pb3;
            split2(p00, p01, pa0, pb0);
            split2(p02, p03, pa1, pb1);
            split2(p10, p11, pa2, pb2);
            split2(p12, p13, pa3, pb3);
            #pragma unroll
            for (int dp = 0; dp < 4; dp++) {
                uint32_t va = stb + 2 * AKV_TILE +
                    (uint32_t)((dp * 16 + b_ro) * A_LDS + t_ * 16 + b_co) * 2;
                uint32_t v0, v1, v2, v3, w0, w1, w2, w3;
                LDMATRIX_X4(v0, v1, v2, v3, va);
                LDMATRIX_X4(w0, w1, w2, w3, va + AKV_TILE);
                float* oa = o[2 * dp]; float* oc = o[2 * dp + 1];
                MMA16816(oa[0], oa[1], oa[2], oa[3], pa0, pa1, pa2, pa3, v0, v1);
                MMA16816(oc[0], oc[1], oc[2], oc[3], pa0, pa1, pa2, pa3, v2, v3);
                MMA16816(oa[0], oa[1], oa[2], oa[3], pa0, pa1, pa2, pa3, w0, w1);
                MMA16816(oc[0], oc[1], oc[2], oc[3], pa0, pa1, pa2, pa3, w2, w3);
                MMA16816(oa[0], oa[1], oa[2], oa[3], pb0, pb1, pb2, pb3, v0, v1);
                MMA16816(oc[0], oc[1], oc[2], oc[3], pb0, pb1, pb2, pb3, v2, v3);
            }
        }
        rs0 += __shfl_xor_sync(0xffffffffu, rs0, 1);
        rs0 += __shfl_xor_sync(0xffffffffu, rs0, 2);
        rs1 += __shfl_xor_sync(0xffffffffu, rs1, 1);
        rs1 += __shfl_xor_sync(0xffffffffu, rs1, 2);
        l0 = l0 * c0 + rs0;
        l1 = l1 * c1 + rs1;
    }

    // ---- epilogue ----
    float inv0 = 1.f / l0, inv1 = 1.f / l1;
    const int er = lane >> 2, ec = (lane & 3) * 2;
    size_t base0 = ((size_t)(b * SEQ + q0 + wid * 16 + er)) * EMBED + h * HDIM;
    size_t base1 = base0 + (size_t)8 * EMBED;
    #pragma unroll
    for (int j = 0; j < 8; j++) {
        uint32_t hi, lo;
        split2(o[j][0] * inv0, o[j][1] * inv0, hi, lo);
        *(uint32_t*)(ohi + base0 + j * 8 + ec) = hi;
        *(uint32_t*)(olo + base0 + j * 8 + ec) = lo;
        split2(o[j][2] * inv1, o[j][3] * inv1, hi, lo);
        *(uint32_t*)(ohi + base1 + j * 8 + ec) = hi;
        *(uint32_t*)(olo + base1 + j * 8 + ec) = lo;
    }
}

// ---------------------------------------------------------------------------
extern "C" void kernel_launch(void* const* d_in, const int* in_sizes, int n_in,
                              void* d_out, int out_size)
{
    const float* x     = (const float*)d_in[0];
    const float* Wqkv  = (const float*)d_in[1];
    const float* bqkv  = (const float*)d_in[2];
    const float* Wproj = (const float*)d_in[3];
    const float* bproj = (const float*)d_in[4];
    float* out = (float*)d_out;

    __nv_bfloat16 *xhi, *xlo, *qh, *ql, *kh, *kl, *vh, *vl, *ahi, *alo;
    __nv_bfloat16 *wqh, *wql, *wph, *wpl;
    cudaGetSymbolAddress((void**)&xhi, g_xhi);  cudaGetSymbolAddress((void**)&xlo, g_xlo);
    cudaGetSymbolAddress((void**)&qh, g_qhi);   cudaGetSymbolAddress((void**)&ql, g_qlo);
    cudaGetSymbolAddress((void**)&kh, g_khi);   cudaGetSymbolAddress((void**)&kl, g_klo);
    cudaGetSymbolAddress((void**)&vh, g_vhi);   cudaGetSymbolAddress((void**)&vl, g_vlo);
    cudaGetSymbolAddress((void**)&ahi, g_ahi);  cudaGetSymbolAddress((void**)&alo, g_alo);
    cudaGetSymbolAddress((void**)&wqh, g_wqkvT_hi);  cudaGetSymbolAddress((void**)&wql, g_wqkvT_lo);
    cudaGetSymbolAddress((void**)&wph, g_wprjT_hi);  cudaGetSymbolAddress((void**)&wpl, g_wprjT_lo);

    cudaFuncSetAttribute(tc_gemm<0>, cudaFuncAttributeMaxDynamicSharedMemorySize, G_SMEM);
    cudaFuncSetAttribute(tc_gemm<1>, cudaFuncAttributeMaxDynamicSharedMemorySize, G_SMEM);
    cudaFuncSetAttribute(attn_mma, cudaFuncAttributeMaxDynamicSharedMemorySize, A_SMEM);

    // 1) conversions
    {
        int n4 = M_TOK * EMBED / 4;
        cvt_split<<<(n4 + 255) / 256, 256>>>(x, xhi, xlo, n4);
        dim3 gq(3 * EMBED / 32, EMBED / 32);
        cvt_transpose<<<gq, 256>>>(Wqkv, wqh, wql, EMBED, 3 * EMBED);
        dim3 gp(EMBED / 32, EMBED / 32);
        cvt_transpose<<<gp, 256>>>(Wproj, wph, wpl, EMBED, EMBED);
    }

    // 2) QKV projection + fused split/transpose epilogue
    {
        dim3 grid(3 * EMBED / 128, M_TOK / 128);
        tc_gemm<1><<<grid, 256, G_SMEM>>>(xhi, xlo, wqh, wql, bqkv, nullptr,
                                          3 * EMBED, EMBED, qh, ql, kh, kl, vh, vl);
    }

    // 3) HMMA flash attention
    {
        dim3 grid(SEQ / 128, NHEAD, BATCH);
        attn_mma<<<grid, 256, A_SMEM>>>(qh, ql, kh, kl, vh, vl, ahi, alo);
    }

    // 4) output projection
    {
        dim3 grid(EMBED / 128, M_TOK / 128);
        tc_gemm<0><<<grid, 256, G_SMEM>>>(ahi, alo, wph, wpl, bproj, out,
                                          EMBED, EMBED,
                                          nullptr, nullptr, nullptr, nullptr, nullptr, nullptr);
    }
}

// round 16
// speedup vs baseline: 1.0156x; 1.0156x over previous
#include <cuda_runtime.h>
#include <cuda_bf16.h>
#include <cstdint>

#define EMBED  1024
#define NHEAD  16
#define HDIM   64
#define BATCH  2
#define SEQ    2048
#define M_TOK  4096
#define SCL2E  0.18033688011112042f   // 0.125 * log2(e)

// ---------------------------------------------------------------------------
// Scratch (device globals — no allocation allowed)
// ---------------------------------------------------------------------------
#define NELEM ((size_t)M_TOK * EMBED)
__device__ __nv_bfloat16 g_xhi[NELEM], g_xlo[NELEM];
__device__ __nv_bfloat16 g_qhi[NELEM], g_qlo[NELEM];      // [b,h,n,d]
__device__ __nv_bfloat16 g_khi[NELEM], g_klo[NELEM];      // [b,h,n,d]
__device__ __nv_bfloat16 g_vhi[NELEM], g_vlo[NELEM];      // [b,h,d,n]
__device__ __nv_bfloat16 g_ahi[NELEM], g_alo[NELEM];      // attn out [tok][C]
__device__ __nv_bfloat16 g_wqkvT_hi[(size_t)3*EMBED*EMBED], g_wqkvT_lo[(size_t)3*EMBED*EMBED];
__device__ __nv_bfloat16 g_wprjT_hi[(size_t)EMBED*EMBED],   g_wprjT_lo[(size_t)EMBED*EMBED];

// ---------------------------------------------------------------------------
// Asm helpers (base-target safe)
// ---------------------------------------------------------------------------
__device__ __forceinline__ uint32_t smem_u32(const void* p) {
    uint32_t a;
    asm("{ .reg .u64 t; cvta.to.shared.u64 t, %1; cvt.u32.u64 %0, t; }" : "=r"(a) : "l"(p));
    return a;
}
#define CP_ASYNC16(s, g) \
    asm volatile("cp.async.cg.shared.global [%0], [%1], 16;" :: "r"(s), "l"(g))
#define CP_COMMIT() asm volatile("cp.async.commit_group;" ::: "memory")
#define CP_WAIT(n)  asm volatile("cp.async.wait_group %0;" :: "n"(n) : "memory")

#define LDMATRIX_X4(r0, r1, r2, r3, a) \
    asm volatile("ldmatrix.sync.aligned.m8n8.x4.shared.b16 {%0,%1,%2,%3}, [%4];" \
                 : "=r"(r0), "=r"(r1), "=r"(r2), "=r"(r3) : "r"(a))

#define MMA16816(c0, c1, c2, c3, a0, a1, a2, a3, b0, b1) \
    asm volatile("mma.sync.aligned.m16n8k16.row.col.f32.bf16.bf16.f32 " \
                 "{%0,%1,%2,%3}, {%4,%5,%6,%7}, {%8,%9}, {%0,%1,%2,%3};" \
                 : "+f"(c0), "+f"(c1), "+f"(c2), "+f"(c3) \
                 : "r"(a0), "r"(a1), "r"(a2), "r"(a3), "r"(b0), "r"(b1))

// exp2 on the FMA pipe (no MUFU)
__device__ __forceinline__ float fexp2(float t) {
    t = fmaxf(t, -30.0f);
    float r = t + 12582912.0f;
    float i = r - 12582912.0f;
    float x = (t - i) * 0.6931471805599453f;
    float p = fmaf(x, 0.0083333333f, 0.0416666667f);
    p = fmaf(x, p, 0.1666666667f);
    p = fmaf(x, p, 0.5f);
    p = fmaf(x, p, 1.0f);
    p = fmaf(x, p, 1.0f);
    int ii = __float_as_int(r) - 0x4B400000;
    return __int_as_float(__float_as_int(p) + (ii << 23));
}

__device__ __forceinline__ void split2(float a, float b, uint32_t& hi, uint32_t& lo) {
    __nv_bfloat162 h2 = __floats2bfloat162_rn(a, b);
    float ra = a - __bfloat162float(__low2bfloat16(h2));
    float rb = b - __bfloat162float(__high2bfloat16(h2));
    __nv_bfloat162 l2 = __floats2bfloat162_rn(ra, rb);
    hi = reinterpret_cast<uint32_t&>(h2);
    lo = reinterpret_cast<uint32_t&>(l2);
}
__device__ __forceinline__ void split1(float v, __nv_bfloat16& h, __nv_bfloat16& l) {
    h = __float2bfloat16(v);
    l = __float2bfloat16(v - __bfloat162float(h));
}

// ---------------------------------------------------------------------------
// conversions
// ---------------------------------------------------------------------------
__global__ __launch_bounds__(256) void cvt_split(
    const float* __restrict__ x, __nv_bfloat16* __restrict__ hi,
    __nv_bfloat16* __restrict__ lo, int n4)
{
    int i = blockIdx.x * blockDim.x + threadIdx.x;
    if (i >= n4) return;
    float4 v = ((const float4*)x)[i];
    __nv_bfloat16 h[4], l[4];
    float f[4] = {v.x, v.y, v.z, v.w};
    #pragma unroll
    for (int j = 0; j < 4; j++) split1(f[j], h[j], l[j]);
    ((uint2*)hi)[i] = *(uint2*)h;
    ((uint2*)lo)[i] = *(uint2*)l;
}

// both weight transposes in ONE launch; blockIdx.z selects the matrix
__global__ __launch_bounds__(256) void cvt_transpose2(
    const float* __restrict__ Wq, __nv_bfloat16* __restrict__ qhi,
    __nv_bfloat16* __restrict__ qlo,
    const float* __restrict__ Wp, __nv_bfloat16* __restrict__ phi,
    __nv_bfloat16* __restrict__ plo)
{
    const float* W;
    __nv_bfloat16 *thi, *tlo;
    int N;
    if (blockIdx.z == 0) { W = Wq; thi = qhi; tlo = qlo; N = 3 * EMBED; }
    else {
        if (blockIdx.x >= EMBED / 32) return;
        W = Wp; thi = phi; tlo = plo; N = EMBED;
    }
    const int K = EMBED;
    __shared__ float t[32][33];
    int tx = threadIdx.x & 31, ty = threadIdx.x >> 5;
    int n0 = blockIdx.x * 32, k0 = blockIdx.y * 32;
    #pragma unroll
    for (int i = 0; i < 4; i++)
        t[ty + i * 8][tx] = W[(size_t)(k0 + ty + i * 8) * N + n0 + tx];
    __syncthreads();
    #pragma unroll
    for (int i = 0; i < 4; i++) {
        float v = t[tx][ty + i * 8];
        __nv_bfloat16 h, l; split1(v, h, l);
        size_t o = (size_t)(n0 + ty + i * 8) * K + k0 + tx;
        thi[o] = h; tlo[o] = l;
    }
}

// ---------------------------------------------------------------------------
// HMMA bf16x3 GEMM — EXACT R8 structure (double-barrier mainloop; the
// trailing __syncthreads is load-bearing: it closes the WAR window between
// this iter's smem reads and next iter's prefetch writes to the same buffer).
// CTA 128x128, BK=32, 8 warps (2M x 4N). 2 CTAs/SM.
// ---------------------------------------------------------------------------
#define G_BK     32
#define G_LDS    40
#define G_TILE_B (128 * G_LDS * 2)
#define G_STAGE  (4 * G_TILE_B)
#define G_SMEM   (2 * G_STAGE)

__device__ __forceinline__ void g_load_stage(
    uint32_t s_stage,
    const __nv_bfloat16* ga_hi, const __nv_bfloat16* ga_lo,
    const __nv_bfloat16* gb_hi, const __nv_bfloat16* gb_lo,
    int k0, int K, int tid)
{
    const __nv_bfloat16* srcs[4] = {ga_hi, ga_lo, gb_hi, gb_lo};
    #pragma unroll
    for (int t = 0; t < 4; t++) {
        #pragma unroll
        for (int i = 0; i < 2; i++) {
            int id = tid + i * 256;
            int r = id >> 2, c = (id & 3) << 3;
            CP_ASYNC16(s_stage + t * G_TILE_B + (uint32_t)(r * G_LDS + c) * 2,
                       srcs[t] + (size_t)r * K + k0 + c);
        }
    }
}

template <int MODE>
__global__ __launch_bounds__(256, 2) void tc_gemm(
    const __nv_bfloat16* __restrict__ Ahi, const __nv_bfloat16* __restrict__ Alo,
    const __nv_bfloat16* __restrict__ Bthi, const __nv_bfloat16* __restrict__ Btlo,
    const float* __restrict__ bias, float* __restrict__ C, int N, int K,
    __nv_bfloat16* qh_o, __nv_bfloat16* ql_o,
    __nv_bfloat16* kh_o, __nv_bfloat16* kl_o,
    __nv_bfloat16* vh_o, __nv_bfloat16* vl_o)
{
    extern __shared__ char smch[];
    const uint32_t s_base = smem_u32(smch);
    const int tid = threadIdx.x;
    const int wid = tid >> 5, lane = tid & 31;
    const int bm = blockIdx.y * 128, bn = blockIdx.x * 128;
    const int wm = (wid & 1) * 64;
    const int wn = (wid >> 1) * 32;

    const __nv_bfloat16* ga_hi = Ahi + (size_t)bm * K;
    const __nv_bfloat16* ga_lo = Alo + (size_t)bm * K;
    const __nv_bfloat16* gb_hi = Bthi + (size_t)bn * K;
    const __nv_bfloat16* gb_lo = Btlo + (size_t)bn * K;

    float acc[4][4][4];
    #pragma unroll
    for (int i = 0; i < 4; i++)
        #pragma unroll
        for (int j = 0; j < 4; j++)
            #pragma unroll
            for (int e = 0; e < 4; e++) acc[i][j][e] = 0.f;

    const int a_row = wm + (lane & 15);
    const uint32_t a_coff = (uint32_t)((lane >> 4) * 16);
    const int grp = lane >> 3;
    const int b_row = wn + ((grp & 2) << 2) + (lane & 7);
    const uint32_t b_coff = (uint32_t)((grp & 1) * 16);

    const int NT = K / G_BK;
    g_load_stage(s_base, ga_hi, ga_lo, gb_hi, gb_lo, 0, K, tid);
    CP_COMMIT();

    for (int it = 0; it < NT; it++) {
        if (it + 1 < NT) {
            g_load_stage(s_base + ((it + 1) & 1) * G_STAGE,
                         ga_hi, ga_lo, gb_hi, gb_lo, (it + 1) * G_BK, K, tid);
            CP_COMMIT();
            CP_WAIT(1);
        } else {
            CP_WAIT(0);
        }
        __syncthreads();

        const uint32_t st = s_base + (it & 1) * G_STAGE;
        #pragma unroll
        for (int ks = 0; ks < 2; ks++) {
            const uint32_t kb = (uint32_t)(ks * 32);
            uint32_t ah[4][4], al[4][4];
            #pragma unroll
            for (int mt = 0; mt < 4; mt++) {
                uint32_t ra = st + (uint32_t)((a_row + mt * 16) * G_LDS) * 2 + kb + a_coff;
                LDMATRIX_X4(ah[mt][0], ah[mt][1], ah[mt][2], ah[mt][3], ra);
                LDMATRIX_X4(al[mt][0], al[mt][1], al[mt][2], al[mt][3], ra + G_TILE_B);
            }
            uint32_t bh[2][4], bl[2][4];
            #pragma unroll
            for (int nt2 = 0; nt2 < 2; nt2++) {
                uint32_t rb = st + 2 * G_TILE_B +
                    (uint32_t)((b_row + nt2 * 16) * G_LDS) * 2 + kb + b_coff;
                LDMATRIX_X4(bh[nt2][0], bh[nt2][1], bh[nt2][2], bh[nt2][3], rb);
                LDMATRIX_X4(bl[nt2][0], bl[nt2][1], bl[nt2][2], bl[nt2][3], rb + G_TILE_B);
            }
            #pragma unroll
            for (int mt = 0; mt < 4; mt++) {
                #pragma unroll
                for (int nt = 0; nt < 4; nt++) {
                    float* c = acc[mt][nt];
                    MMA16816(c[0], c[1], c[2], c[3],
                             ah[mt][0], ah[mt][1], ah[mt][2], ah[mt][3],
                             bh[nt >> 1][(nt & 1) * 2], bh[nt >> 1][(nt & 1) * 2 + 1]);
                }
            }
            #pragma unroll
            for (int mt = 0; mt < 4; mt++) {
                #pragma unroll
                for (int nt = 0; nt < 4; nt++) {
                    float* c = acc[mt][nt];
                    MMA16816(c[0], c[1], c[2], c[3],
                             ah[mt][0], ah[mt][1], ah[mt][2], ah[mt][3],
                             bl[nt >> 1][(nt & 1) * 2], bl[nt >> 1][(nt & 1) * 2 + 1]);
                }
            }
            #pragma unroll
            for (int mt = 0; mt < 4; mt++) {
                #pragma unroll
                for (int nt = 0; nt < 4; nt++) {
                    float* c = acc[mt][nt];
                    MMA16816(c[0], c[1], c[2], c[3],
                             al[mt][0], al[mt][1], al[mt][2], al[mt][3],
                             bh[nt >> 1][(nt & 1) * 2], bh[nt >> 1][(nt & 1) * 2 + 1]);
                }
            }
        }
        __syncthreads();   // WAR guard: reads of this buffer done before next prefetch
    }

    const int er = lane >> 2;
    const int ec = (lane & 3) * 2;
    #pragma unroll
    for (int nt = 0; nt < 4; nt++) {
        int col = bn + wn + nt * 8 + ec;
        float bs0 = __ldg(bias + col), bs1 = __ldg(bias + col + 1);
        if (MODE == 0) {
            #pragma unroll
            for (int mt = 0; mt < 4; mt++) {
                int row = bm + wm + mt * 16 + er;
                float2 v0 = {acc[mt][nt][0] + bs0, acc[mt][nt][1] + bs1};
                float2 v1 = {acc[mt][nt][2] + bs0, acc[mt][nt][3] + bs1};
                *(float2*)(C + (size_t)row * N + col) = v0;
                *(float2*)(C + (size_t)(row + 8) * N + col) = v1;
            }
        } else {
            int p = col >> 10;
            int hh = (col & 1023) >> 6;
            int d = col & 63;
            #pragma unroll
            for (int mt = 0; mt < 4; mt++) {
                int row = bm + wm + mt * 16 + er;
                int bb = row >> 11, n = row & 2047;
                float v0 = acc[mt][nt][0] + bs0, v1 = acc[mt][nt][1] + bs1;
                float v2 = acc[mt][nt][2] + bs0, v3 = acc[mt][nt][3] + bs1;
                if (p == 0) { v0 *= SCL2E; v1 *= SCL2E; v2 *= SCL2E; v3 *= SCL2E; }
                if (p < 2) {
                    __nv_bfloat16* dh = p ? kh_o : qh_o;
                    __nv_bfloat16* dl = p ? kl_o : ql_o;
                    size_t i0 = ((size_t)(bb * NHEAD + hh) * SEQ + n) * HDIM + d;
                    uint32_t hi, lo;
                    split2(v0, v1, hi, lo);
                    *(uint32_t*)(dh + i0) = hi;  *(uint32_t*)(dl + i0) = lo;
                    split2(v2, v3, hi, lo);
                    *(uint32_t*)(dh + i0 + 8 * HDIM) = hi;  *(uint32_t*)(dl + i0 + 8 * HDIM) = lo;
                } else {
                    size_t i0 = ((size_t)(bb * NHEAD + hh) * HDIM + d) * SEQ + n;
                    __nv_bfloat16 h, l;
                    split1(v0, h, l); vh_o[i0] = h;            vl_o[i0] = l;
                    split1(v1, h, l); vh_o[i0 + SEQ] = h;      vl_o[i0 + SEQ] = l;
                    split1(v2, h, l); vh_o[i0 + 8] = h;        vl_o[i0 + 8] = l;
                    split1(v3, h, l); vh_o[i0 + SEQ + 8] = h;  vl_o[i0 + SEQ + 8] = l;
                }
            }
        }
    }
}

// ---------------------------------------------------------------------------
// HMMA flash attention (bf16 3-term, R8 config — passing). CTA = 128 q rows.
// Single-barrier loop is safe here: barrier sits between wait and prefetch.
// ---------------------------------------------------------------------------
#define A_LDS    72
#define AQ_TILE  (128 * A_LDS * 2)          // 18432 B per Q array
#define AKV_TILE (64 * A_LDS * 2)           // 9216 B per KV array
#define A_ST0    (2 * AQ_TILE)              // 36864
#define A_STAGE  (4 * AKV_TILE)             // 36864
#define A_SMEM   (A_ST0 + 2 * A_STAGE)      // 110592 B

__global__ __launch_bounds__(256, 2) void attn_mma(
    const __nv_bfloat16* __restrict__ qhi, const __nv_bfloat16* __restrict__ qlo,
    const __nv_bfloat16* __restrict__ khi, const __nv_bfloat16* __restrict__ klo,
    const __nv_bfloat16* __restrict__ vhi, const __nv_bfloat16* __restrict__ vlo,
    __nv_bfloat16* __restrict__ ohi, __nv_bfloat16* __restrict__ olo)
{
    extern __shared__ char smch[];
    const uint32_t sb = smem_u32(smch);
    const int tid = threadIdx.x, wid = tid >> 5, lane = tid & 31;
    const int b = blockIdx.z, h = blockIdx.y, q0 = blockIdx.x * 128;
    const size_t bh = (size_t)(b * NHEAD + h);

    const __nv_bfloat16* gq_h = qhi + (bh * SEQ + q0) * HDIM;
    const __nv_bfloat16* gq_l = qlo + (bh * SEQ + q0) * HDIM;
    const __nv_bfloat16* gk_h = khi + bh * SEQ * HDIM;
    const __nv_bfloat16* gk_l = klo + bh * SEQ * HDIM;
    const __nv_bfloat16* gv_h = vhi + bh * HDIM * SEQ;
    const __nv_bfloat16* gv_l = vlo + bh * HDIM * SEQ;

    #pragma unroll
    for (int i = 0; i < 8; i++) {
        int id = tid + i * 256;
        int arr = id >> 10, rem = id & 1023;
        int r = rem >> 3, c = (rem & 7) * 8;
        uint32_t dst = sb + arr * AQ_TILE + (uint32_t)(r * A_LDS + c) * 2;
        CP_ASYNC16(dst, (arr ? gq_l : gq_h) + (size_t)r * HDIM + c);
    }
    {
        uint32_t st = sb + A_ST0;
        #pragma unroll
        for (int i = 0; i < 8; i++) {
            int id = tid + i * 256;
            int arr = id >> 9, rem = id & 511;
            int r = rem >> 3, c = (rem & 7) * 8;
            uint32_t dst = st + arr * AKV_TILE + (uint32_t)(r * A_LDS + c) * 2;
            const __nv_bfloat16* src;
            if      (arr == 0) src = gk_h + (size_t)r * HDIM + c;
            else if (arr == 1) src = gk_l + (size_t)r * HDIM + c;
            else if (arr == 2) src = gv_h + (size_t)r * SEQ + c;
            else               src = gv_l + (size_t)r * SEQ + c;
            CP_ASYNC16(dst, src);
        }
    }
    CP_COMMIT();

    const int g = lane >> 3, rr = lane & 7;
    const int a_ro = wid * 16 + ((g & 1) << 3) + rr;
    const int a_co = (g >> 1) << 3;
    const int b_ro = ((g >> 1) << 3) + rr;
    const int b_co = (g & 1) << 3;

    uint32_t qh_[4][4];
    float o[8][4];
    #pragma unroll
    for (int j = 0; j < 8; j++)
        #pragma unroll
        for (int e = 0; e < 4; e++) o[j][e] = 0.f;
    float m0 = -1e30f, m1 = -1e30f, l0 = 0.f, l1 = 0.f;

    const int NT = SEQ / 64;
    for (int t = 0; t < NT; t++) {
        CP_WAIT(0);
        __syncthreads();

        if (t + 1 < NT) {
            uint32_t st = sb + A_ST0 + ((t + 1) & 1) * A_STAGE;
            int kv0 = (t + 1) * 64;
            #pragma unroll
            for (int i = 0; i < 8; i++) {
                int id = tid + i * 256;
                int arr = id >> 9, rem = id & 511;
                int r = rem >> 3, c = (rem & 7) * 8;
                uint32_t dst = st + arr * AKV_TILE + (uint32_t)(r * A_LDS + c) * 2;
                const __nv_bfloat16* src;
                if      (arr == 0) src = gk_h + (size_t)(kv0 + r) * HDIM + c;
                else if (arr == 1) src = gk_l + (size_t)(kv0 + r) * HDIM + c;
                else if (arr == 2) src = gv_h + (size_t)r * SEQ + kv0 + c;
                else               src = gv_l + (size_t)r * SEQ + kv0 + c;
                CP_ASYNC16(dst, src);
            }
            CP_COMMIT();
        }

        if (t == 0) {
            #pragma unroll
            for (int ks = 0; ks < 4; ks++) {
                uint32_t ad = sb + (uint32_t)(a_ro * A_LDS + ks * 16 + a_co) * 2;
                LDMATRIX_X4(qh_[ks][0], qh_[ks][1], qh_[ks][2], qh_[ks][3], ad);
            }
        }

        const uint32_t stb = sb + A_ST0 + (t & 1) * A_STAGE;

        // ---- S = Q' @ K^T (3-split), interleaved sa/sc chains ----
        float s[8][4];
        #pragma unroll
        for (int j = 0; j < 8; j++)
            #pragma unroll
            for (int e = 0; e < 4; e++) s[j][e] = 0.f;

        #pragma unroll
        for (int ks = 0; ks < 4; ks++) {
            uint32_t ql0, ql1, ql2, ql3;
            uint32_t qa = sb + AQ_TILE + (uint32_t)(a_ro * A_LDS + ks * 16 + a_co) * 2;
            LDMATRIX_X4(ql0, ql1, ql2, ql3, qa);
            #pragma unroll
            for (int np = 0; np < 4; np++) {
                uint32_t ka = stb + (uint32_t)((np * 16 + b_ro) * A_LDS + ks * 16 + b_co) * 2;
                uint32_t k0, k1, k2, k3, e0, e1, e2, e3;
                LDMATRIX_X4(k0, k1, k2, k3, ka);
                LDMATRIX_X4(e0, e1, e2, e3, ka + AKV_TILE);
                float* sa = s[2 * np]; float* sc = s[2 * np + 1];
                MMA16816(sa[0], sa[1], sa[2], sa[3],
                         qh_[ks][0], qh_[ks][1], qh_[ks][2], qh_[ks][3], k0, k1);
                MMA16816(sc[0], sc[1], sc[2], sc[3],
                         qh_[ks][0], qh_[ks][1], qh_[ks][2], qh_[ks][3], k2, k3);
                MMA16816(sa[0], sa[1], sa[2], sa[3],
                         qh_[ks][0], qh_[ks][1], qh_[ks][2], qh_[ks][3], e0, e1);
                MMA16816(sc[0], sc[1], sc[2], sc[3],
                         qh_[ks][0], qh_[ks][1], qh_[ks][2], qh_[ks][3], e2, e3);
                MMA16816(sa[0], sa[1], sa[2], sa[3], ql0, ql1, ql2, ql3, k0, k1);
                MMA16816(sc[0], sc[1], sc[2], sc[3], ql0, ql1, ql2, ql3, k2, k3);
            }
        }

        // ---- online softmax ----
        float mt0 = -1e30f, mt1 = -1e30f;
        #pragma unroll
        for (int j = 0; j < 8; j++) {
            mt0 = fmaxf(mt0, fmaxf(s[j][0], s[j][1]));
            mt1 = fmaxf(mt1, fmaxf(s[j][2], s[j][3]));
        }
        mt0 = fmaxf(mt0, __shfl_xor_sync(0xffffffffu, mt0, 1));
        mt0 = fmaxf(mt0, __shfl_xor_sync(0xffffffffu, mt0, 2));
        mt1 = fmaxf(mt1, __shfl_xor_sync(0xffffffffu, mt1, 1));
        mt1 = fmaxf(mt1, __shfl_xor_sync(0xffffffffu, mt1, 2));
        float nm0 = fmaxf(m0, mt0), nm1 = fmaxf(m1, mt1);
        float c0 = fexp2(m0 - nm0), c1 = fexp2(m1 - nm1);
        m0 = nm0; m1 = nm1;
        #pragma unroll
        for (int j = 0; j < 8; j++) {
            o[j][0] *= c0; o[j][1] *= c0; o[j][2] *= c1; o[j][3] *= c1;
        }
        float rs0 = 0.f, rs1 = 0.f;

        // ---- stream P -> PV (3-split), interleaved oa/oc chains ----
        #pragma unroll
        for (int t_ = 0; t_ < 4; t_++) {
            int j0 = 2 * t_, j1 = 2 * t_ + 1;
            float p00 = fexp2(s[j0][0] - nm0), p01 = fexp2(s[j0][1] - nm0);
            float p02 = fexp2(s[j0][2] - nm1), p03 = fexp2(s[j0][3] - nm1);
            float p10 = fexp2(s[j1][0] - nm0), p11 = fexp2(s[j1][1] - nm0);
            float p12 = fexp2(s[j1][2] - nm1), p13 = fexp2(s[j1][3] - nm1);
            rs0 += p00 + p01 + p10 + p11;
            rs1 += p02 + p03 + p12 + p13;
            uint32_t pa0, pa1, pa2, pa3, pb0, pb1, pb2, pb3;
            split2(p00, p01, pa0, pb0);
            split2(p02, p03, pa1, pb1);
            split2(p10, p11, pa2, pb2);
            split2(p12, p13, pa3, pb3);
            #pragma unroll
            for (int dp = 0; dp < 4; dp++) {
                uint32_t va = stb + 2 * AKV_TILE +
                    (uint32_t)((dp * 16 + b_ro) * A_LDS + t_ * 16 + b_co) * 2;
                uint32_t v0, v1, v2, v3, w0, w1, w2, w3;
                LDMATRIX_X4(v0, v1, v2, v3, va);
                LDMATRIX_X4(w0, w1, w2, w3, va + AKV_TILE);
                float* oa = o[2 * dp]; float* oc = o[2 * dp + 1];
                MMA16816(oa[0], oa[1], oa[2], oa[3], pa0, pa1, pa2, pa3, v0, v1);
                MMA16816(oc[0], oc[1], oc[2], oc[3], pa0, pa1, pa2, pa3, v2, v3);
                MMA16816(oa[0], oa[1], oa[2], oa[3], pa0, pa1, pa2, pa3, w0, w1);
                MMA16816(oc[0], oc[1], oc[2], oc[3], pa0, pa1, pa2, pa3, w2, w3);
                MMA16816(oa[0], oa[1], oa[2], oa[3], pb0, pb1, pb2, pb3, v0, v1);
                MMA16816(oc[0], oc[1], oc[2], oc[3], pb0, pb1, pb2, pb3, v2, v3);
            }
        }
        rs0 += __shfl_xor_sync(0xffffffffu, rs0, 1);
        rs0 += __shfl_xor_sync(0xffffffffu, rs0, 2);
        rs1 += __shfl_xor_sync(0xffffffffu, rs1, 1);
        rs1 += __shfl_xor_sync(0xffffffffu, rs1, 2);
        l0 = l0 * c0 + rs0;
        l1 = l1 * c1 + rs1;
    }

    // ---- epilogue ----
    float inv0 = 1.f / l0, inv1 = 1.f / l1;
    const int er = lane >> 2, ec = (lane & 3) * 2;
    size_t base0 = ((size_t)(b * SEQ + q0 + wid * 16 + er)) * EMBED + h * HDIM;
    size_t base1 = base0 + (size_t)8 * EMBED;
    #pragma unroll
    for (int j = 0; j < 8; j++) {
        uint32_t hi, lo;
        split2(o[j][0] * inv0, o[j][1] * inv0, hi, lo);
        *(uint32_t*)(ohi + base0 + j * 8 + ec) = hi;
        *(uint32_t*)(olo + base0 + j * 8 + ec) = lo;
        split2(o[j][2] * inv1, o[j][3] * inv1, hi, lo);
        *(uint32_t*)(ohi + base1 + j * 8 + ec) = hi;
        *(uint32_t*)(olo + base1 + j * 8 + ec) = lo;
    }
}

// ---------------------------------------------------------------------------
extern "C" void kernel_launch(void* const* d_in, const int* in_sizes, int n_in,
                              void* d_out, int out_size)
{
    const float* x     = (const float*)d_in[0];
    const float* Wqkv  = (const float*)d_in[1];
    const float* bqkv  = (const float*)d_in[2];
    const float* Wproj = (const float*)d_in[3];
    const float* bproj = (const float*)d_in[4];
    float* out = (float*)d_out;

    __nv_bfloat16 *xhi, *xlo, *qh, *ql, *kh, *kl, *vh, *vl, *ahi, *alo;
    __nv_bfloat16 *wqh, *wql, *wph, *wpl;
    cudaGetSymbolAddress((void**)&xhi, g_xhi);  cudaGetSymbolAddress((void**)&xlo, g_xlo);
    cudaGetSymbolAddress((void**)&qh, g_qhi);   cudaGetSymbolAddress((void**)&ql, g_qlo);
    cudaGetSymbolAddress((void**)&kh, g_khi);   cudaGetSymbolAddress((void**)&kl, g_klo);
    cudaGetSymbolAddress((void**)&vh, g_vhi);   cudaGetSymbolAddress((void**)&vl, g_vlo);
    cudaGetSymbolAddress((void**)&ahi, g_ahi);  cudaGetSymbolAddress((void**)&alo, g_alo);
    cudaGetSymbolAddress((void**)&wqh, g_wqkvT_hi);  cudaGetSymbolAddress((void**)&wql, g_wqkvT_lo);
    cudaGetSymbolAddress((void**)&wph, g_wprjT_hi);  cudaGetSymbolAddress((void**)&wpl, g_wprjT_lo);

    cudaFuncSetAttribute(tc_gemm<0>, cudaFuncAttributeMaxDynamicSharedMemorySize, G_SMEM);
    cudaFuncSetAttribute(tc_gemm<1>, cudaFuncAttributeMaxDynamicSharedMemorySize, G_SMEM);
    cudaFuncSetAttribute(attn_mma, cudaFuncAttributeMaxDynamicSharedMemorySize, A_SMEM);

    // 1) conversions (x split + BOTH weight transposes in one launch)
    {
        int n4 = M_TOK * EMBED / 4;
        cvt_split<<<(n4 + 255) / 256, 256>>>(x, xhi, xlo, n4);
        dim3 gt(3 * EMBED / 32, EMBED / 32, 2);
        cvt_transpose2<<<gt, 256>>>(Wqkv, wqh, wql, Wproj, wph, wpl);
    }

    // 2) QKV projection + fused split/transpose epilogue
    {
        dim3 grid(3 * EMBED / 128, M_TOK / 128);
        tc_gemm<1><<<grid, 256, G_SMEM>>>(xhi, xlo, wqh, wql, bqkv, nullptr,
                                          3 * EMBED, EMBED, qh, ql, kh, kl, vh, vl);
    }

    // 3) HMMA flash attention
    {
        dim3 grid(SEQ / 128, NHEAD, BATCH);
        attn_mma<<<grid, 256, A_SMEM>>>(qh, ql, kh, kl, vh, vl, ahi, alo);
    }

    // 4) output projection
    {
        dim3 grid(EMBED / 128, M_TOK / 128);
        tc_gemm<0><<<grid, 256, G_SMEM>>>(ahi, alo, wph, wpl, bproj, out,
                                          EMBED, EMBED,
                                          nullptr, nullptr, nullptr, nullptr, nullptr, nullptr);
    }
}